// round 1
// baseline (speedup 1.0000x reference)
#include <cuda_runtime.h>
#include <math.h>

// MFHawkes: O(B*L*D) factorized Hawkes log-likelihood.
//   t = times/1e4, ab = |beta|
//   v[d]      = sum_j (1 - exp(-ab*(t_last - t_j))) * e_j[d]           (all j)
//   P_i[d]    = sum_{j<i} exp(ab*t_j) * mask_j * e_j[d]                (exclusive prefix)
//   S1_i      = ab * exp(-ab*t_i) * (e_i . P_i)
//   S2_i      = e_i . v
//   lam_i     = |S1_i + u_i| + 1e-6
//   out[b]    = sum_i ( -log(lam_i) + u_i*horizon + S2_i ),  horizon = t_last - t[1]

#define HK_L    2048
#define HK_D    64
#define HK_NW   32            // warps per block
#define HK_CHUNK (HK_L/HK_NW) // 64 events per warp-chunk

__global__ __launch_bounds__(1024, 1)
void mfhawkes_kernel(const int*   __restrict__ ids,
                     const float* __restrict__ times,
                     const float* __restrict__ mask,
                     const float* __restrict__ emb,
                     const float* __restrict__ u_table,
                     const float* __restrict__ beta,
                     float*       __restrict__ out)
{
    __shared__ float  t_sh[HK_L];
    __shared__ float  T_sh[HK_NW][HK_D];   // chunk totals -> exclusive bases (in place)
    __shared__ float  V_sh[HK_NW][HK_D];   // per-chunk partials of v
    __shared__ float  v_sh[HK_D];
    __shared__ double acc_sh[HK_NW];

    const int b    = blockIdx.x;
    const int tid  = threadIdx.x;
    const int warp = tid >> 5;
    const int lane = tid & 31;

    const int*   idb = ids  + b * HK_L;
    const float* mb  = mask + b * HK_L;

    // load + normalize times
    for (int i = tid; i < HK_L; i += blockDim.x)
        t_sh[i] = times[b * HK_L + i] * (1.0f / 10000.0f);
    __syncthreads();

    const float ab      = fabsf(beta[0]);
    const float tlast   = t_sh[HK_L - 1];
    const float horizon = tlast - t_sh[1];

    // ---- Phase A: per-chunk totals T_c[d] = sum w_j*e_j[d], V_c[d] = sum g_j*e_j[d]
    {
        const int c = warp;
        float T0 = 0.f, T1 = 0.f, V0 = 0.f, V1 = 0.f;
        #pragma unroll 4
        for (int jj = 0; jj < HK_CHUNK; jj++) {
            const int   j  = c * HK_CHUNK + jj;
            const int   id = idb[j];
            const float tj = t_sh[j];
            const float w  = expf(ab * tj) * mb[j];                 // mask folded into prefix weight
            const float g  = 1.0f - expf(ab * (tj - tlast));        // 1 - exp(-ab*(tlast-tj))
            const float e0 = emb[id * HK_D + lane];
            const float e1 = emb[id * HK_D + lane + 32];
            T0 += w * e0;  T1 += w * e1;
            V0 += g * e0;  V1 += g * e1;
        }
        T_sh[c][lane]      = T0;  T_sh[c][lane + 32] = T1;
        V_sh[c][lane]      = V0;  V_sh[c][lane + 32] = V1;
    }
    __syncthreads();

    // ---- Phase B: exclusive scan of chunk totals per dim; reduce v
    if (tid < HK_D) {
        float run = 0.f, vv = 0.f;
        #pragma unroll
        for (int c = 0; c < HK_NW; c++) {
            const float tmp = T_sh[c][tid];
            T_sh[c][tid] = run;        // exclusive base for chunk c
            run += tmp;
            vv  += V_sh[c][tid];
        }
        v_sh[tid] = vv;
    }
    __syncthreads();

    // ---- Phase C: per-chunk sequential scan, two dots per event
    {
        const int c  = warp;
        float P0 = T_sh[c][lane], P1 = T_sh[c][lane + 32];
        const float v0 = v_sh[lane], v1 = v_sh[lane + 32];
        double acc = 0.0;
        for (int ii = 0; ii < HK_CHUNK; ii++) {
            const int   i  = c * HK_CHUNK + ii;
            const int   id = idb[i];
            const float e0 = emb[id * HK_D + lane];
            const float e1 = emb[id * HK_D + lane + 32];
            float d1 = e0 * P0 + e1 * P1;   // partial of e_i . P_i
            float d2 = e0 * v0 + e1 * v1;   // partial of e_i . v
            #pragma unroll
            for (int off = 16; off; off >>= 1) {
                d1 += __shfl_xor_sync(0xffffffffu, d1, off);
                d2 += __shfl_xor_sync(0xffffffffu, d2, off);
            }
            const float ti  = t_sh[i];
            const float u   = fabsf(u_table[id]);
            const float S1  = ab * expf(-ab * ti) * d1;
            const float lam = fabsf(S1 + u) + 1e-6f;
            acc += (double)(-logf(lam) + u * horizon + d2);
            const float w = expf(ab * ti) * mb[i];
            P0 += w * e0;  P1 += w * e1;
        }
        if (lane == 0) acc_sh[warp] = acc;
    }
    __syncthreads();

    // ---- final reduce across warps
    if (warp == 0) {
        double a = (lane < HK_NW) ? acc_sh[lane] : 0.0;
        #pragma unroll
        for (int off = 16; off; off >>= 1)
            a += __shfl_xor_sync(0xffffffffu, a, off);
        if (lane == 0) out[b] = (float)a;
    }
}

extern "C" void kernel_launch(void* const* d_in, const int* in_sizes, int n_in,
                              void* d_out, int out_size)
{
    const int*   ids     = (const int*)  d_in[0];  // identities (B,L) int32
    const float* times   = (const float*)d_in[1];  // times      (B,L)
    const float* mask    = (const float*)d_in[2];  // mask       (B,1,L)
    const float* emb     = (const float*)d_in[3];  // emb        (K,D)
    const float* u_table = (const float*)d_in[4];  // u_table    (K,)
    const float* beta    = (const float*)d_in[5];  // beta       (1,)
    float*       out     = (float*)d_out;          // (B,)

    const int B = in_sizes[0] / HK_L;              // 4
    mfhawkes_kernel<<<B, 1024>>>(ids, times, mask, emb, u_table, beta, out);
}

// round 2
// speedup vs baseline: 1.5675x; 1.5675x over previous
#include <cuda_runtime.h>
#include <math.h>

// MFHawkes factorized O(B*L*D), 3-kernel latency-optimized version.
//   t = times/1e4, ab = |beta|
//   w_j = exp(ab*t_j)*mask_j ;  g_j = 1 - exp(-ab*(t_last - t_j))
//   P_i = sum_{j<i} w_j e_j (exclusive prefix) ; v = sum_j g_j e_j
//   S1_i = ab*exp(-ab*t_i)*(e_i.P_i) ; lam = |S1+u_i|+1e-6
//   out[b] = sum_i ( -log(lam_i) + u_i*horizon + e_i.v )

#define HK_L     2048
#define HK_D     64
#define HK_B     4
#define HK_CHUNK 16
#define HK_NCH   (HK_L / HK_CHUNK)        // 128 chunks per batch
#define HK_WPB   8                         // warps per block (k1,k3)
#define HK_GRID  ((HK_B * HK_NCH) / HK_WPB) // 64 blocks

__device__ float hk_T[HK_B * HK_NCH * HK_D];   // chunk totals of w*e
__device__ float hk_V[HK_B * HK_NCH * HK_D];   // chunk totals of g*e
__device__ float hk_Base[HK_B * HK_NCH * HK_D];// exclusive prefix bases
__device__ float hk_v[HK_B * HK_D];            // v per batch

// ---------------- k1: per-chunk totals ----------------
__global__ __launch_bounds__(HK_WPB * 32, 1)
void hk_k1(const int*   __restrict__ ids,
           const float* __restrict__ times,
           const float* __restrict__ mask,
           const float* __restrict__ emb,
           const float* __restrict__ beta,
           float*       __restrict__ out)
{
    const int warp = threadIdx.x >> 5;
    const int lane = threadIdx.x & 31;
    const int gid  = blockIdx.x * HK_WPB + warp;   // 0..511
    const int b    = gid >> 7;                     // /128
    const int c    = gid & (HK_NCH - 1);

    const float ab    = fabsf(beta[0]);
    const float tlast = times[b * HK_L + HK_L - 1] * (1.0f / 10000.0f);

    if (c == 0 && lane == 0) out[b] = 0.0f;

    float T0 = 0.f, T1 = 0.f, V0 = 0.f, V1 = 0.f;
    const int j0 = c * HK_CHUNK;
    #pragma unroll
    for (int jj = 0; jj < HK_CHUNK; jj++) {
        const int   j  = j0 + jj;
        const int   id = ids[b * HK_L + j];
        const float tj = times[b * HK_L + j] * (1.0f / 10000.0f);
        const float w  = expf(ab * tj) * mask[b * HK_L + j];
        const float g  = 1.0f - expf(ab * (tj - tlast));
        const float e0 = emb[id * HK_D + lane];
        const float e1 = emb[id * HK_D + lane + 32];
        T0 += w * e0;  T1 += w * e1;
        V0 += g * e0;  V1 += g * e1;
    }
    hk_T[gid * HK_D + lane]      = T0;
    hk_T[gid * HK_D + lane + 32] = T1;
    hk_V[gid * HK_D + lane]      = V0;
    hk_V[gid * HK_D + lane + 32] = V1;
}

// ---------------- k2: exclusive scan over chunks + v ----------------
__global__ __launch_bounds__(HK_D, 1)
void hk_k2()
{
    const int b = blockIdx.x;
    const int d = threadIdx.x;          // 0..63
    float run = 0.f, vv = 0.f;
    const int base = b * HK_NCH * HK_D;
    #pragma unroll 8
    for (int c = 0; c < HK_NCH; c++) {
        const int idx = base + c * HK_D + d;
        const float tt = hk_T[idx];
        hk_Base[idx] = run;
        run += tt;
        vv  += hk_V[idx];
    }
    hk_v[b * HK_D + d] = vv;
}

// ---------------- k3: per-chunk sequential scan + reduce ----------------
__global__ __launch_bounds__(HK_WPB * 32, 1)
void hk_k3(const int*   __restrict__ ids,
           const float* __restrict__ times,
           const float* __restrict__ mask,
           const float* __restrict__ emb,
           const float* __restrict__ u_table,
           const float* __restrict__ beta,
           float*       __restrict__ out)
{
    __shared__ double racc[HK_WPB];

    const int warp = threadIdx.x >> 5;
    const int lane = threadIdx.x & 31;
    const int gid  = blockIdx.x * HK_WPB + warp;
    const int b    = gid >> 7;
    const int c    = gid & (HK_NCH - 1);

    const float ab      = fabsf(beta[0]);
    const float tlast   = times[b * HK_L + HK_L - 1] * (1.0f / 10000.0f);
    const float horizon = tlast - times[b * HK_L + 1] * (1.0f / 10000.0f);

    float P0 = hk_Base[gid * HK_D + lane];
    float P1 = hk_Base[gid * HK_D + lane + 32];
    const float v0 = hk_v[b * HK_D + lane];
    const float v1 = hk_v[b * HK_D + lane + 32];

    double acc = 0.0;
    const int i0 = c * HK_CHUNK;
    #pragma unroll
    for (int ii = 0; ii < HK_CHUNK; ii++) {
        const int   i  = i0 + ii;
        const int   id = ids[b * HK_L + i];
        const float ti = times[b * HK_L + i] * (1.0f / 10000.0f);
        const float e0 = emb[id * HK_D + lane];
        const float e1 = emb[id * HK_D + lane + 32];
        float d1 = e0 * P0 + e1 * P1;
        float d2 = e0 * v0 + e1 * v1;
        #pragma unroll
        for (int off = 16; off; off >>= 1) {
            d1 += __shfl_xor_sync(0xffffffffu, d1, off);
            d2 += __shfl_xor_sync(0xffffffffu, d2, off);
        }
        const float u   = fabsf(u_table[id]);
        const float S1  = ab * expf(-ab * ti) * d1;
        const float lam = fabsf(S1 + u) + 1e-6f;
        acc += (double)(-logf(lam) + u * horizon + d2);
        const float w = expf(ab * ti) * mask[b * HK_L + i];
        P0 += w * e0;  P1 += w * e1;
    }
    if (lane == 0) racc[warp] = acc;
    __syncthreads();

    if (warp == 0) {
        double a = (lane < HK_WPB) ? racc[lane] : 0.0;
        #pragma unroll
        for (int off = 4; off; off >>= 1)
            a += __shfl_xor_sync(0xffffffffu, a, off);
        if (lane == 0) atomicAdd(&out[b], (float)a);
    }
}

extern "C" void kernel_launch(void* const* d_in, const int* in_sizes, int n_in,
                              void* d_out, int out_size)
{
    const int*   ids     = (const int*)  d_in[0];
    const float* times   = (const float*)d_in[1];
    const float* mask    = (const float*)d_in[2];
    const float* emb     = (const float*)d_in[3];
    const float* u_table = (const float*)d_in[4];
    const float* beta    = (const float*)d_in[5];
    float*       out     = (float*)d_out;

    hk_k1<<<HK_GRID, HK_WPB * 32>>>(ids, times, mask, emb, beta, out);
    hk_k2<<<HK_B, HK_D>>>();
    hk_k3<<<HK_GRID, HK_WPB * 32>>>(ids, times, mask, emb, u_table, beta, out);
}

// round 3
// speedup vs baseline: 4.9542x; 3.1605x over previous
#include <cuda_runtime.h>
#include <math.h>

// MFHawkes factorized O(B*L*D), single fused kernel with grid-wide barrier.
//   t = times/1e4, ab = |beta|
//   w_j = exp(ab*t_j)*mask_j ;  g_j = 1 - exp(-ab*(t_last - t_j))
//   P_i = sum_{j<i} w_j e_j (exclusive prefix) ; v = sum_j g_j e_j
//   S1_i = ab*exp(-ab*t_i)*(e_i.P_i) ; lam = |S1+u_i|+1e-6
//   out[b] = sum_i ( -log(lam_i) + u_i*horizon + e_i.v )

#define HK_L     2048
#define HK_D     64
#define HK_B     4
#define HK_CHUNK 8                      // events per warp
#define HK_WPB   8                      // warps per block
#define HK_EPB   (HK_WPB * HK_CHUNK)    // 64 events per block
#define HK_BPB   (HK_L / HK_EPB)        // 32 blocks per batch
#define HK_NBLK  (HK_B * HK_BPB)        // 128 blocks total

__device__ float    g_blkT[HK_NBLK * HK_D];
__device__ float    g_blkV[HK_NBLK * HK_D];
__device__ unsigned g_count = 0;
__device__ volatile unsigned g_flag = 0;

__device__ __forceinline__ void grid_sync()
{
    __syncthreads();
    if (threadIdx.x == 0) {
        const unsigned old = g_flag;
        __threadfence();
        const unsigned n = atomicAdd(&g_count, 1u);
        if (n == gridDim.x - 1) {
            g_count = 0;                 // self-reset for next graph replay
            __threadfence();
            g_flag = old + 1;            // release
        } else {
            while (g_flag == old) { }
            __threadfence();
        }
    }
    __syncthreads();
}

__global__ __launch_bounds__(HK_WPB * 32, 1)
void mfhawkes_fused(const int*   __restrict__ ids,
                    const float* __restrict__ times,
                    const float* __restrict__ mask,
                    const float* __restrict__ emb,
                    const float* __restrict__ u_table,
                    const float* __restrict__ beta,
                    float*       __restrict__ out)
{
    __shared__ float  Tsm[HK_WPB][HK_D];
    __shared__ float  Vsm[HK_WPB][HK_D];
    __shared__ float  basesm[HK_D];
    __shared__ float  vsm[HK_D];
    __shared__ double racc[HK_WPB];

    const int warp   = threadIdx.x >> 5;
    const int lane   = threadIdx.x & 31;
    const int batch  = blockIdx.x / HK_BPB;
    const int blk_in = blockIdx.x % HK_BPB;

    const float ab      = fabsf(beta[0]);
    const float tlast   = times[batch * HK_L + HK_L - 1] * (1.0f / 10000.0f);
    const float horizon = tlast - times[batch * HK_L + 1] * (1.0f / 10000.0f);

    if (blk_in == 0 && threadIdx.x == 0) out[batch] = 0.0f;

    // ---- Phase A: gather embeddings into registers, per-warp chunk totals
    const int i0 = batch * HK_L + blk_in * HK_EPB + warp * HK_CHUNK;

    float e0[HK_CHUNK], e1[HK_CHUNK], w[HK_CHUNK], u[HK_CHUNK], kx[HK_CHUNK];
    float T0 = 0.f, T1 = 0.f, V0 = 0.f, V1 = 0.f;
    #pragma unroll
    for (int i = 0; i < HK_CHUNK; i++) {
        const int   id = ids[i0 + i];
        const float ti = times[i0 + i] * (1.0f / 10000.0f);
        const float wm = mask[i0 + i];
        e0[i] = emb[id * HK_D + lane];
        e1[i] = emb[id * HK_D + lane + 32];
        u[i]  = fabsf(u_table[id]);
        const float ep = __expf(ab * ti);
        w[i]  = ep * wm;                          // prefix weight (mask folded)
        kx[i] = ab * __expf(-ab * ti);            // ab * exp(-ab*t_i)
        const float g = 1.0f - __expf(ab * (ti - tlast));
        T0 += w[i] * e0[i];  T1 += w[i] * e1[i];
        V0 += g    * e0[i];  V1 += g    * e1[i];
    }
    Tsm[warp][lane]      = T0;  Tsm[warp][lane + 32] = T1;
    Vsm[warp][lane]      = V0;  Vsm[warp][lane + 32] = V1;
    __syncthreads();

    // ---- intra-block exclusive scan over warps + block totals to global
    if (threadIdx.x < HK_D) {
        const int d = threadIdx.x;
        float run = 0.f, vv = 0.f;
        #pragma unroll
        for (int c = 0; c < HK_WPB; c++) {
            const float tt = Tsm[c][d];
            Tsm[c][d] = run;             // warp-exclusive base within block
            run += tt;
            vv  += Vsm[c][d];
        }
        g_blkT[blockIdx.x * HK_D + d] = run;
        g_blkV[blockIdx.x * HK_D + d] = vv;
    }

    grid_sync();

    // ---- cross-block exclusive scan (within batch) + v reduction
    if (threadIdx.x < HK_D) {
        const int d = threadIdx.x;
        float base = 0.f, vv = 0.f;
        #pragma unroll
        for (int k = 0; k < HK_BPB; k++) {
            const float tb = g_blkT[(batch * HK_BPB + k) * HK_D + d];
            const float tv = g_blkV[(batch * HK_BPB + k) * HK_D + d];
            if (k < blk_in) base += tb;
            vv += tv;
        }
        basesm[d] = base;
        vsm[d]    = vv;
    }
    __syncthreads();

    // ---- Phase C: 8-step serial scan per warp, embeddings already in regs
    {
        float P0 = basesm[lane]      + Tsm[warp][lane];
        float P1 = basesm[lane + 32] + Tsm[warp][lane + 32];
        const float v0 = vsm[lane], v1 = vsm[lane + 32];
        double acc = 0.0;
        #pragma unroll
        for (int i = 0; i < HK_CHUNK; i++) {
            float d1 = e0[i] * P0 + e1[i] * P1;
            float d2 = e0[i] * v0 + e1[i] * v1;
            #pragma unroll
            for (int off = 16; off; off >>= 1) {
                d1 += __shfl_xor_sync(0xffffffffu, d1, off);
                d2 += __shfl_xor_sync(0xffffffffu, d2, off);
            }
            const float lam = fabsf(kx[i] * d1 + u[i]) + 1e-6f;
            acc += (double)(-__logf(lam) + u[i] * horizon + d2);
            P0 += w[i] * e0[i];
            P1 += w[i] * e1[i];
        }
        if (lane == 0) racc[warp] = acc;
    }
    __syncthreads();

    if (warp == 0) {
        double a = (lane < HK_WPB) ? racc[lane] : 0.0;
        #pragma unroll
        for (int off = 4; off; off >>= 1)
            a += __shfl_xor_sync(0xffffffffu, a, off);
        if (lane == 0) atomicAdd(&out[batch], (float)a);
    }
}

extern "C" void kernel_launch(void* const* d_in, const int* in_sizes, int n_in,
                              void* d_out, int out_size)
{
    const int*   ids     = (const int*)  d_in[0];
    const float* times   = (const float*)d_in[1];
    const float* mask    = (const float*)d_in[2];
    const float* emb     = (const float*)d_in[3];
    const float* u_table = (const float*)d_in[4];
    const float* beta    = (const float*)d_in[5];
    float*       out     = (float*)d_out;

    mfhawkes_fused<<<HK_NBLK, HK_WPB * 32>>>(ids, times, mask, emb, u_table, beta, out);
}